// round 11
// baseline (speedup 1.0000x reference)
#include <cuda_runtime.h>
#include <cstdint>

#define BATCH 2
#define SEQ 2048
#define HID 2048
#define NH 32
#define NKV 8
#define HD 64
#define HALF 32
#define NREP 4
#define GK 2048
#define CHUNK 32
#define NCHUNK (GK / CHUNK)
#define NQKV 3072          // fused QKV output width

// ---------------- scratch (static device globals; no allocation) -------------
__device__ float g_q[BATCH * NH * SEQ * HD];     // roped, scaled  [B,H,S,D]
__device__ float g_k[BATCH * NKV * SEQ * HD];    // roped          [B,KV,S,D]
__device__ float g_v[BATCH * NKV * SEQ * HD];    // [B,KV,S,D]
__device__ float g_ao[BATCH * SEQ * HID];        // attn out [B,S,H*D]
__device__ float g_wqkvT[NQKV * HID];            // [wq^T; wk^T; wv^T]
__device__ float g_woT[HID * HID];               // wo^T

// ---------------- helpers ----------------------------------------------------
__device__ __forceinline__ uint32_t f2tf(float x) {
    uint32_t r;
    asm("cvt.rna.tf32.f32 %0, %1;" : "=r"(r) : "f"(x));
    return r;
}
__device__ __forceinline__ float ex2(float x) {
    float r;
    asm("ex2.approx.f32 %0, %1;" : "=f"(r) : "f"(x));
    return r;
}

#define MMA_TF32(d, a, b)                                                      \
    asm volatile("mma.sync.aligned.m16n8k8.row.col.f32.tf32.tf32.f32 "         \
        "{%0,%1,%2,%3}, {%4,%5,%6,%7}, {%8,%9}, {%0,%1,%2,%3};"                \
        : "+f"((d)[0]), "+f"((d)[1]), "+f"((d)[2]), "+f"((d)[3])               \
        : "r"((a)[0]), "r"((a)[1]), "r"((a)[2]), "r"((a)[3]),                  \
          "r"((b)[0]), "r"((b)[1]))

// ---------------- weight transpose: out[C][R] = in[R][C] ---------------------
__global__ void transpose_kernel(const float* __restrict__ in, float* __restrict__ out,
                                 int R, int C) {
    __shared__ float t[32][33];
    int bx = blockIdx.x * 32, by = blockIdx.y * 32;
#pragma unroll
    for (int j = 0; j < 32; j += 8)
        t[threadIdx.y + j][threadIdx.x] =
            in[(size_t)(by + threadIdx.y + j) * C + bx + threadIdx.x];
    __syncthreads();
#pragma unroll
    for (int j = 0; j < 32; j += 8)
        out[(size_t)(bx + threadIdx.y + j) * R + by + threadIdx.x] =
            t[threadIdx.x][threadIdx.y + j];
}

// ---------------- shared GEMM mainloop (macro to reuse in 2 kernels) ----------
#define APAD 36
#define TILE_F (128 * APAD)
#define GEMM_SMEM (2 * 2 * TILE_F * 4)

#define GEMM_MAINLOOP(Aptr, Bptr)                                              \
    float acc[4][4][4];                                                        \
    _Pragma("unroll")                                                          \
    for (int mi = 0; mi < 4; mi++)                                             \
        _Pragma("unroll")                                                      \
        for (int ni = 0; ni < 4; ni++)                                         \
            _Pragma("unroll")                                                  \
            for (int e = 0; e < 4; e++) acc[mi][ni][e] = 0.0f;                 \
    float4 av[4], bv[4];                                                       \
    _Pragma("unroll")                                                          \
    for (int p = 0; p < 4; p++) {                                              \
        int row = p * 32 + lrow;                                               \
        av[p] = *(const float4*)(Aptr + (size_t)row * GK + lc4);               \
        bv[p] = *(const float4*)(Bptr + (size_t)row * GK + lc4);               \
    }                                                                          \
    {                                                                          \
        uint32_t* As = smem;                                                   \
        uint32_t* Bs = smem + TILE_F;                                          \
        _Pragma("unroll")                                                      \
        for (int p = 0; p < 4; p++) {                                          \
            int row = p * 32 + lrow;                                           \
            uint32_t* ap = As + row * APAD + lc4;                              \
            ap[0] = f2tf(av[p].x); ap[1] = f2tf(av[p].y);                      \
            ap[2] = f2tf(av[p].z); ap[3] = f2tf(av[p].w);                      \
            uint32_t* bp = Bs + row * APAD + lc4;                              \
            bp[0] = f2tf(bv[p].x); bp[1] = f2tf(bv[p].y);                      \
            bp[2] = f2tf(bv[p].z); bp[3] = f2tf(bv[p].w);                      \
        }                                                                      \
    }                                                                          \
    __syncthreads();                                                           \
    for (int i = 0; i < NCHUNK; i++) {                                         \
        if (i + 1 < NCHUNK) {                                                  \
            int k0 = (i + 1) * CHUNK;                                          \
            _Pragma("unroll")                                                  \
            for (int p = 0; p < 4; p++) {                                      \
                int row = p * 32 + lrow;                                       \
                av[p] = *(const float4*)(Aptr + (size_t)row * GK + k0 + lc4);  \
                bv[p] = *(const float4*)(Bptr + (size_t)row * GK + k0 + lc4);  \
            }                                                                  \
        }                                                                      \
        {                                                                      \
            uint32_t* As = smem + (i & 1) * 2 * TILE_F;                        \
            uint32_t* Bs = As + TILE_F;                                        \
            _Pragma("unroll")                                                  \
            for (int ks = 0; ks < 4; ks++) {                                   \
                int kk = ks * 8;                                               \
                uint32_t afr[4][4];                                            \
                _Pragma("unroll")                                              \
                for (int mi = 0; mi < 4; mi++) {                               \
                    int r0 = wm + mi * 16 + g;                                 \
                    afr[mi][0] = As[r0 * APAD + kk + t];                       \
                    afr[mi][1] = As[(r0 + 8) * APAD + kk + t];                 \
                    afr[mi][2] = As[r0 * APAD + kk + t + 4];                   \
                    afr[mi][3] = As[(r0 + 8) * APAD + kk + t + 4];             \
                }                                                              \
                uint32_t bfr[4][2];                                            \
                _Pragma("unroll")                                              \
                for (int ni = 0; ni < 4; ni++) {                               \
                    int n0 = wn + ni * 8 + g;                                  \
                    bfr[ni][0] = Bs[n0 * APAD + kk + t];                       \
                    bfr[ni][1] = Bs[n0 * APAD + kk + t + 4];                   \
                }                                                              \
                _Pragma("unroll")                                              \
                for (int mi = 0; mi < 4; mi++)                                 \
                    _Pragma("unroll")                                          \
                    for (int ni = 0; ni < 4; ni++)                             \
                        MMA_TF32(acc[mi][ni], afr[mi], bfr[ni]);               \
            }                                                                  \
        }                                                                      \
        if (i + 1 < NCHUNK) {                                                  \
            __syncthreads();                                                   \
            uint32_t* As = smem + ((i + 1) & 1) * 2 * TILE_F;                  \
            uint32_t* Bs = As + TILE_F;                                        \
            _Pragma("unroll")                                                  \
            for (int p = 0; p < 4; p++) {                                      \
                int row = p * 32 + lrow;                                       \
                uint32_t* ap = As + row * APAD + lc4;                          \
                ap[0] = f2tf(av[p].x); ap[1] = f2tf(av[p].y);                  \
                ap[2] = f2tf(av[p].z); ap[3] = f2tf(av[p].w);                  \
                uint32_t* bp = Bs + row * APAD + lc4;                          \
                bp[0] = f2tf(bv[p].x); bp[1] = f2tf(bv[p].y);                  \
                bp[2] = f2tf(bv[p].z); bp[3] = f2tf(bv[p].w);                  \
            }                                                                  \
            __syncthreads();                                                   \
        }                                                                      \
    }

// ---------------- plain GEMM (output projection) ------------------------------
__global__ __launch_bounds__(256)
void tf32_gemm(const float* __restrict__ A, const float* __restrict__ BT,
               float* __restrict__ C, int N) {
    extern __shared__ uint32_t smem[];
    int tid = threadIdx.x;
    int w = tid >> 5, lane = tid & 31;
    int g = lane >> 2, t = lane & 3;
    int wm = (w >> 2) * 64, wn = (w & 3) * 32;
    int bm = blockIdx.y * 128, bn = blockIdx.x * 128;
    const float* Ab = A + (size_t)bm * GK;
    const float* Bb = BT + (size_t)bn * GK;
    int lrow = tid >> 3, lc4 = (tid & 7) << 2;

    GEMM_MAINLOOP(Ab, Bb)

#pragma unroll
    for (int mi = 0; mi < 4; mi++) {
#pragma unroll
        for (int ni = 0; ni < 4; ni++) {
            int r0 = bm + wm + mi * 16 + g;
            int c0 = bn + wn + ni * 8 + t * 2;
            *(float2*)(C + (size_t)r0 * N + c0) =
                make_float2(acc[mi][ni][0], acc[mi][ni][1]);
            *(float2*)(C + (size_t)(r0 + 8) * N + c0) =
                make_float2(acc[mi][ni][2], acc[mi][ni][3]);
        }
    }
}

// ---------------- fused QKV GEMM + RoPE epilogue ------------------------------
// log2(e) folded into Q so attention can use ex2 directly.
#define QSCALE (0.125f * 1.44269504088896f)

__device__ __forceinline__ void qkv_write_pair(
    float* gq, float* gk, float* gv,
    const float* __restrict__ fc, const float* __restrict__ fs,
    int r, int c, float e0, float e1) {
    int b = r >> 11, s = r & 2047;
    if (c < HID) {                       // Q + rope + scale
        int h = c >> 6, d = c & 63, p = d >> 1;
        float cs = fc[s * HALF + p], sn = fs[s * HALF + p];
        *(float2*)(gq + ((size_t)(b * NH + h) * SEQ + s) * HD + d) =
            make_float2((e0 * cs - e1 * sn) * QSCALE,
                        (e0 * sn + e1 * cs) * QSCALE);
    } else if (c < HID + NKV * HD) {     // K + rope
        int cc = c - HID;
        int kvh = cc >> 6, d = cc & 63, p = d >> 1;
        float cs = fc[s * HALF + p], sn = fs[s * HALF + p];
        *(float2*)(gk + ((size_t)(b * NKV + kvh) * SEQ + s) * HD + d) =
            make_float2(e0 * cs - e1 * sn, e0 * sn + e1 * cs);
    } else {                             // V copy
        int cc = c - HID - NKV * HD;
        int kvh = cc >> 6, d = cc & 63;
        *(float2*)(gv + ((size_t)(b * NKV + kvh) * SEQ + s) * HD + d) =
            make_float2(e0, e1);
    }
}

__global__ __launch_bounds__(256)
void qkv_rope_gemm(const float* __restrict__ A, const float* __restrict__ BT,
                   float* __restrict__ gq, float* __restrict__ gk,
                   float* __restrict__ gv,
                   const float* __restrict__ fc, const float* __restrict__ fs) {
    extern __shared__ uint32_t smem[];
    int tid = threadIdx.x;
    int w = tid >> 5, lane = tid & 31;
    int g = lane >> 2, t = lane & 3;
    int wm = (w >> 2) * 64, wn = (w & 3) * 32;
    int bm = blockIdx.y * 128, bn = blockIdx.x * 128;
    const float* Ab = A + (size_t)bm * GK;
    const float* Bb = BT + (size_t)bn * GK;
    int lrow = tid >> 3, lc4 = (tid & 7) << 2;

    GEMM_MAINLOOP(Ab, Bb)

#pragma unroll
    for (int mi = 0; mi < 4; mi++) {
#pragma unroll
        for (int ni = 0; ni < 4; ni++) {
            int r0 = bm + wm + mi * 16 + g;
            int c0 = bn + wn + ni * 8 + t * 2;
            qkv_write_pair(gq, gk, gv, fc, fs, r0, c0,
                           acc[mi][ni][0], acc[mi][ni][1]);
            qkv_write_pair(gq, gk, gv, fc, fs, r0 + 8, c0,
                           acc[mi][ni][2], acc[mi][ni][3]);
        }
    }
}

// ---------------- tensor-core flash attention v2 ------------------------------
// CTA: 128 q-rows x one (b,h), 8 warps x 16 rows. K-tile = 64 keys.
// Q fragments in registers; K/V double-buffered smem with register prefetch;
// one __syncthreads per tile. Softmax in log2 domain (scale folded upstream).
#define K2P 68
#define V2P 72
#define SM2_VS (2 * 64 * K2P)
#define SM2_PS (SM2_VS + 2 * 64 * V2P)
#define ATTN2_SMEM ((SM2_PS + 8 * 16 * K2P) * 4)

__global__ __launch_bounds__(256)
void attn_tc2_kernel(const float* __restrict__ Q, const float* __restrict__ K,
                     const float* __restrict__ V, float* __restrict__ O) {
    extern __shared__ uint32_t sm[];
    uint32_t* KsB = sm;
    uint32_t* VsB = sm + SM2_VS;
    uint32_t* Ps  = sm + SM2_PS;

    int tid = threadIdx.x;
    int w = tid >> 5, lane = tid & 31;
    int g = lane >> 2, t = lane & 3;
    int qt = gridDim.x - 1 - blockIdx.x;     // longest first
    int bh = blockIdx.y;
    int b = bh >> 5, h = bh & 31;
    int kvh = h >> 2;
    int q0 = qt * 128;
    int qrow = w * 16;

    const float* Qb = Q + ((size_t)(b * NH + h) * SEQ + q0) * HD;
    const float* Kb = K + (size_t)(b * NKV + kvh) * SEQ * HD;
    const float* Vb = V + (size_t)(b * NKV + kvh) * SEQ * HD;

    // Q fragments -> registers (once)
    uint32_t qf[8][4];
#pragma unroll
    for (int ks = 0; ks < 8; ks++) {
        int kk = ks * 8;
        qf[ks][0] = f2tf(Qb[(qrow + g) * HD + kk + t]);
        qf[ks][1] = f2tf(Qb[(qrow + 8 + g) * HD + kk + t]);
        qf[ks][2] = f2tf(Qb[(qrow + g) * HD + kk + t + 4]);
        qf[ks][3] = f2tf(Qb[(qrow + 8 + g) * HD + kk + t + 4]);
    }

    float oacc[8][4];
#pragma unroll
    for (int ni = 0; ni < 8; ni++)
#pragma unroll
        for (int e = 0; e < 4; e++) oacc[ni][e] = 0.0f;
    float m0 = -1e30f, m1 = -1e30f, l0 = 0.0f, l1 = 0.0f;

    int ktmax = (q0 >> 6) + 1;
    int ldrow = tid >> 4, ldc4 = (tid & 15) << 2;

    // preload tile 0
    float4 kv[4], vv[4];
#pragma unroll
    for (int p = 0; p < 4; p++) {
        int row = p * 16 + ldrow;
        kv[p] = *(const float4*)(Kb + (size_t)row * HD + ldc4);
        vv[p] = *(const float4*)(Vb + (size_t)row * HD + ldc4);
    }
#pragma unroll
    for (int p = 0; p < 4; p++) {
        int row = p * 16 + ldrow;
        uint32_t* kp_ = KsB + row * K2P + ldc4;
        kp_[0] = f2tf(kv[p].x); kp_[1] = f2tf(kv[p].y);
        kp_[2] = f2tf(kv[p].z); kp_[3] = f2tf(kv[p].w);
        uint32_t* vp_ = VsB + row * V2P + ldc4;
        vp_[0] = f2tf(vv[p].x); vp_[1] = f2tf(vv[p].y);
        vp_[2] = f2tf(vv[p].z); vp_[3] = f2tf(vv[p].w);
    }
    __syncthreads();

    for (int kt = 0; kt <= ktmax; kt++) {
        int cur = kt & 1;
        if (kt < ktmax) {   // prefetch next tile to registers
            const float* Kp = Kb + (size_t)(kt + 1) * 64 * HD;
            const float* Vp = Vb + (size_t)(kt + 1) * 64 * HD;
#pragma unroll
            for (int p = 0; p < 4; p++) {
                int row = p * 16 + ldrow;
                kv[p] = *(const float4*)(Kp + (size_t)row * HD + ldc4);
                vv[p] = *(const float4*)(Vp + (size_t)row * HD + ldc4);
            }
        }
        uint32_t* Kc = KsB + cur * 64 * K2P;
        uint32_t* Vc = VsB + cur * 64 * V2P;

        // ---- S = Q K^T ----
        float sa[8][4];
#pragma unroll
        for (int ni = 0; ni < 8; ni++)
#pragma unroll
            for (int e = 0; e < 4; e++) sa[ni][e] = 0.0f;
#pragma unroll
        for (int ks = 0; ks < 8; ks++) {
            int kk = ks * 8;
#pragma unroll
            for (int ni = 0; ni < 8; ni++) {
                uint32_t bfr[2];
                bfr[0] = Kc[(ni * 8 + g) * K2P + kk + t];
                bfr[1] = Kc[(ni * 8 + g) * K2P + kk + t + 4];
                MMA_TF32(sa[ni], qf[ks], bfr);
            }
        }

        // ---- causal mask ----
        int r0 = q0 + qrow + g, r1 = r0 + 8;
        if (kt * 64 + 63 > r0) {
            int cb = kt * 64;
#pragma unroll
            for (int ni = 0; ni < 8; ni++) {
                int c0 = cb + ni * 8 + 2 * t, c1 = c0 + 1;
                if (c0 > r0) sa[ni][0] = -1e30f;
                if (c1 > r0) sa[ni][1] = -1e30f;
                if (c0 > r1) sa[ni][2] = -1e30f;
                if (c1 > r1) sa[ni][3] = -1e30f;
            }
        }

        // ---- online softmax (log2 domain) ----
        float mx0 = -1e30f, mx1 = -1e30f;
#pragma unroll
        for (int ni = 0; ni < 8; ni++) {
            mx0 = fmaxf(mx0, fmaxf(sa[ni][0], sa[ni][1]));
            mx1 = fmaxf(mx1, fmaxf(sa[ni][2], sa[ni][3]));
        }
        mx0 = fmaxf(mx0, __shfl_xor_sync(0xffffffffu, mx0, 1));
        mx0 = fmaxf(mx0, __shfl_xor_sync(0xffffffffu, mx0, 2));
        mx1 = fmaxf(mx1, __shfl_xor_sync(0xffffffffu, mx1, 1));
        mx1 = fmaxf(mx1, __shfl_xor_sync(0xffffffffu, mx1, 2));
        float mn0 = fmaxf(m0, mx0), mn1 = fmaxf(m1, mx1);
        float sc0 = ex2(m0 - mn0), sc1 = ex2(m1 - mn1);
        m0 = mn0; m1 = mn1;
        float sum0 = 0.0f, sum1 = 0.0f;
#pragma unroll
        for (int ni = 0; ni < 8; ni++) {
            sa[ni][0] = ex2(sa[ni][0] - mn0); sum0 += sa[ni][0];
            sa[ni][1] = ex2(sa[ni][1] - mn0); sum0 += sa[ni][1];
            sa[ni][2] = ex2(sa[ni][2] - mn1); sum1 += sa[ni][2];
            sa[ni][3] = ex2(sa[ni][3] - mn1); sum1 += sa[ni][3];
        }
        sum0 += __shfl_xor_sync(0xffffffffu, sum0, 1);
        sum0 += __shfl_xor_sync(0xffffffffu, sum0, 2);
        sum1 += __shfl_xor_sync(0xffffffffu, sum1, 1);
        sum1 += __shfl_xor_sync(0xffffffffu, sum1, 2);
        l0 = l0 * sc0 + sum0;
        l1 = l1 * sc1 + sum1;
#pragma unroll
        for (int ni = 0; ni < 8; ni++) {
            oacc[ni][0] *= sc0; oacc[ni][1] *= sc0;
            oacc[ni][2] *= sc1; oacc[ni][3] *= sc1;
        }

        // ---- P -> smem (per-warp region) ----
        uint32_t* Pw = Ps + w * 16 * K2P;
#pragma unroll
        for (int ni = 0; ni < 8; ni++) {
            int c = ni * 8 + 2 * t;
            Pw[g * K2P + c]       = f2tf(sa[ni][0]);
            Pw[g * K2P + c + 1]   = f2tf(sa[ni][1]);
            Pw[(g + 8) * K2P + c]     = f2tf(sa[ni][2]);
            Pw[(g + 8) * K2P + c + 1] = f2tf(sa[ni][3]);
        }
        __syncwarp();

        // ---- O += P V ----
#pragma unroll
        for (int ks = 0; ks < 8; ks++) {
            int kk = ks * 8;
            uint32_t a[4];
            a[0] = Pw[g * K2P + kk + t];
            a[1] = Pw[(g + 8) * K2P + kk + t];
            a[2] = Pw[g * K2P + kk + t + 4];
            a[3] = Pw[(g + 8) * K2P + kk + t + 4];
#pragma unroll
            for (int ni = 0; ni < 8; ni++) {
                uint32_t bfr[2];
                bfr[0] = Vc[(kk + t) * V2P + ni * 8 + g];
                bfr[1] = Vc[(kk + t + 4) * V2P + ni * 8 + g];
                MMA_TF32(oacc[ni], a, bfr);
            }
        }
        __syncwarp();

        // ---- stage next tile into alternate buffer; single barrier ----
        if (kt < ktmax) {
            uint32_t* Kn = KsB + (1 - cur) * 64 * K2P;
            uint32_t* Vn = VsB + (1 - cur) * 64 * V2P;
#pragma unroll
            for (int p = 0; p < 4; p++) {
                int row = p * 16 + ldrow;
                uint32_t* kp_ = Kn + row * K2P + ldc4;
                kp_[0] = f2tf(kv[p].x); kp_[1] = f2tf(kv[p].y);
                kp_[2] = f2tf(kv[p].z); kp_[3] = f2tf(kv[p].w);
                uint32_t* vp_ = Vn + row * V2P + ldc4;
                vp_[0] = f2tf(vv[p].x); vp_[1] = f2tf(vv[p].y);
                vp_[2] = f2tf(vv[p].z); vp_[3] = f2tf(vv[p].w);
            }
            __syncthreads();
        }
    }

    // ---- normalize + write [B,S,H*D] ----
    float rl0 = 1.0f / l0, rl1 = 1.0f / l1;
    int r0 = q0 + qrow + g, r1 = r0 + 8;
#pragma unroll
    for (int ni = 0; ni < 8; ni++) {
        int col = ni * 8 + 2 * t;
        *(float2*)(O + ((size_t)(b * SEQ + r0) * NH + h) * HD + col) =
            make_float2(oacc[ni][0] * rl0, oacc[ni][1] * rl0);
        *(float2*)(O + ((size_t)(b * SEQ + r1) * NH + h) * HD + col) =
            make_float2(oacc[ni][2] * rl1, oacc[ni][3] * rl1);
    }
}

// ---------------- launcher ---------------------------------------------------
extern "C" void kernel_launch(void* const* d_in, const int* in_sizes, int n_in,
                              void* d_out, int out_size) {
    const float* x  = (const float*)d_in[0];
    const float* wq = (const float*)d_in[1];
    const float* wk = (const float*)d_in[2];
    const float* wv = (const float*)d_in[3];
    const float* wo = (const float*)d_in[4];
    const float* fc = (const float*)d_in[5];
    const float* fs = (const float*)d_in[6];
    float* out = (float*)d_out;

    float *q, *k, *v, *ao, *wqkvT, *woT;
    cudaGetSymbolAddress((void**)&q,  g_q);
    cudaGetSymbolAddress((void**)&k,  g_k);
    cudaGetSymbolAddress((void**)&v,  g_v);
    cudaGetSymbolAddress((void**)&ao, g_ao);
    cudaGetSymbolAddress((void**)&wqkvT, g_wqkvT);
    cudaGetSymbolAddress((void**)&woT, g_woT);

    const int M = BATCH * SEQ;  // 4096

    // transposed weights: wqkvT = [wq^T; wk^T; wv^T] (rows = output cols)
    transpose_kernel<<<dim3(HID / 32, HID / 32), dim3(32, 8)>>>(wq, wqkvT, HID, HID);
    transpose_kernel<<<dim3((NKV * HD) / 32, HID / 32), dim3(32, 8)>>>(
        wk, wqkvT + (size_t)HID * HID, HID, NKV * HD);
    transpose_kernel<<<dim3((NKV * HD) / 32, HID / 32), dim3(32, 8)>>>(
        wv, wqkvT + (size_t)(HID + NKV * HD) * HID, HID, NKV * HD);
    transpose_kernel<<<dim3(HID / 32, HID / 32), dim3(32, 8)>>>(wo, woT, HID, HID);

    cudaFuncSetAttribute(qkv_rope_gemm, cudaFuncAttributeMaxDynamicSharedMemorySize,
                         GEMM_SMEM);
    cudaFuncSetAttribute(tf32_gemm, cudaFuncAttributeMaxDynamicSharedMemorySize,
                         GEMM_SMEM);

    // fused QKV projection + RoPE epilogue
    qkv_rope_gemm<<<dim3(NQKV / 128, M / 128), 256, GEMM_SMEM>>>(
        x, wqkvT, q, k, v, fc, fs);

    // flash attention (tf32 tensor cores, double-buffered)
    cudaFuncSetAttribute(attn_tc2_kernel, cudaFuncAttributeMaxDynamicSharedMemorySize,
                         ATTN2_SMEM);
    attn_tc2_kernel<<<dim3(SEQ / 128, BATCH * NH), 256, ATTN2_SMEM>>>(q, k, v, ao);

    // output projection
    tf32_gemm<<<dim3(HID / 128, M / 128), 256, GEMM_SMEM>>>(ao, woT, out, HID);
}

// round 13
// speedup vs baseline: 1.0076x; 1.0076x over previous
#include <cuda_runtime.h>
#include <cstdint>

#define BATCH 2
#define SEQ 2048
#define HID 2048
#define NH 32
#define NKV 8
#define HD 64
#define HALF 32
#define NREP 4
#define GK 2048
#define CHUNK 32
#define NCHUNK (GK / CHUNK)
#define NQKV 3072

// ---------------- scratch (static device globals; no allocation) -------------
__device__ float g_q[BATCH * NH * SEQ * HD];
__device__ float g_k[BATCH * NKV * SEQ * HD];
__device__ float g_v[BATCH * NKV * SEQ * HD];
__device__ float g_ao[BATCH * SEQ * HID];
__device__ float g_wqkvT[NQKV * HID];
__device__ float g_woT[HID * HID];

// ---------------- helpers ----------------------------------------------------
__device__ __forceinline__ uint32_t f2tf(float x) {
    uint32_t r;
    asm("cvt.rna.tf32.f32 %0, %1;" : "=r"(r) : "f"(x));
    return r;
}
__device__ __forceinline__ float ex2(float x) {
    float r;
    asm("ex2.approx.f32 %0, %1;" : "=f"(r) : "f"(x));
    return r;
}

#define MMA_TF32(d, a, b)                                                      \
    asm volatile("mma.sync.aligned.m16n8k8.row.col.f32.tf32.tf32.f32 "         \
        "{%0,%1,%2,%3}, {%4,%5,%6,%7}, {%8,%9}, {%0,%1,%2,%3};"                \
        : "+f"((d)[0]), "+f"((d)[1]), "+f"((d)[2]), "+f"((d)[3])               \
        : "r"((a)[0]), "r"((a)[1]), "r"((a)[2]), "r"((a)[3]),                  \
          "r"((b)[0]), "r"((b)[1]))

// ---------------- weight transpose: out[C][R] = in[R][C] ---------------------
__global__ void transpose_kernel(const float* __restrict__ in, float* __restrict__ out,
                                 int R, int C) {
    __shared__ float t[32][33];
    int bx = blockIdx.x * 32, by = blockIdx.y * 32;
#pragma unroll
    for (int j = 0; j < 32; j += 8)
        t[threadIdx.y + j][threadIdx.x] =
            in[(size_t)(by + threadIdx.y + j) * C + bx + threadIdx.x];
    __syncthreads();
#pragma unroll
    for (int j = 0; j < 32; j += 8)
        out[(size_t)(bx + threadIdx.y + j) * R + by + threadIdx.x] =
            t[threadIdx.x][threadIdx.y + j];
}

// ---------------- shared GEMM mainloop ---------------------------------------
#define APAD 36
#define TILE_F (128 * APAD)
#define GEMM_SMEM (2 * 2 * TILE_F * 4)

#define GEMM_MAINLOOP(Aptr, Bptr)                                              \
    float acc[4][4][4];                                                        \
    _Pragma("unroll")                                                          \
    for (int mi = 0; mi < 4; mi++)                                             \
        _Pragma("unroll")                                                      \
        for (int ni = 0; ni < 4; ni++)                                         \
            _Pragma("unroll")                                                  \
            for (int e = 0; e < 4; e++) acc[mi][ni][e] = 0.0f;                 \
    float4 av[4], bv[4];                                                       \
    _Pragma("unroll")                                                          \
    for (int p = 0; p < 4; p++) {                                              \
        int row = p * 32 + lrow;                                               \
        av[p] = *(const float4*)(Aptr + (size_t)row * GK + lc4);               \
        bv[p] = *(const float4*)(Bptr + (size_t)row * GK + lc4);               \
    }                                                                          \
    {                                                                          \
        uint32_t* As = smem;                                                   \
        uint32_t* Bs = smem + TILE_F;                                          \
        _Pragma("unroll")                                                      \
        for (int p = 0; p < 4; p++) {                                          \
            int row = p * 32 + lrow;                                           \
            uint32_t* ap = As + row * APAD + lc4;                              \
            ap[0] = f2tf(av[p].x); ap[1] = f2tf(av[p].y);                      \
            ap[2] = f2tf(av[p].z); ap[3] = f2tf(av[p].w);                      \
            uint32_t* bp = Bs + row * APAD + lc4;                              \
            bp[0] = f2tf(bv[p].x); bp[1] = f2tf(bv[p].y);                      \
            bp[2] = f2tf(bv[p].z); bp[3] = f2tf(bv[p].w);                      \
        }                                                                      \
    }                                                                          \
    __syncthreads();                                                           \
    for (int i = 0; i < NCHUNK; i++) {                                         \
        if (i + 1 < NCHUNK) {                                                  \
            int k0 = (i + 1) * CHUNK;                                          \
            _Pragma("unroll")                                                  \
            for (int p = 0; p < 4; p++) {                                      \
                int row = p * 32 + lrow;                                       \
                av[p] = *(const float4*)(Aptr + (size_t)row * GK + k0 + lc4);  \
                bv[p] = *(const float4*)(Bptr + (size_t)row * GK + k0 + lc4);  \
            }                                                                  \
        }                                                                      \
        {                                                                      \
            uint32_t* As = smem + (i & 1) * 2 * TILE_F;                        \
            uint32_t* Bs = As + TILE_F;                                        \
            _Pragma("unroll")                                                  \
            for (int ks = 0; ks < 4; ks++) {                                   \
                int kk = ks * 8;                                               \
                uint32_t afr[4][4];                                            \
                _Pragma("unroll")                                              \
                for (int mi = 0; mi < 4; mi++) {                               \
                    int r0 = wm + mi * 16 + g;                                 \
                    afr[mi][0] = As[r0 * APAD + kk + t];                       \
                    afr[mi][1] = As[(r0 + 8) * APAD + kk + t];                 \
                    afr[mi][2] = As[r0 * APAD + kk + t + 4];                   \
                    afr[mi][3] = As[(r0 + 8) * APAD + kk + t + 4];             \
                }                                                              \
                uint32_t bfr[4][2];                                            \
                _Pragma("unroll")                                              \
                for (int ni = 0; ni < 4; ni++) {                               \
                    int n0 = wn + ni * 8 + g;                                  \
                    bfr[ni][0] = Bs[n0 * APAD + kk + t];                       \
                    bfr[ni][1] = Bs[n0 * APAD + kk + t + 4];                   \
                }                                                              \
                _Pragma("unroll")                                              \
                for (int mi = 0; mi < 4; mi++)                                 \
                    _Pragma("unroll")                                          \
                    for (int ni = 0; ni < 4; ni++)                             \
                        MMA_TF32(acc[mi][ni], afr[mi], bfr[ni]);               \
            }                                                                  \
        }                                                                      \
        if (i + 1 < NCHUNK) {                                                  \
            __syncthreads();                                                   \
            uint32_t* As = smem + ((i + 1) & 1) * 2 * TILE_F;                  \
            uint32_t* Bs = As + TILE_F;                                        \
            _Pragma("unroll")                                                  \
            for (int p = 0; p < 4; p++) {                                      \
                int row = p * 32 + lrow;                                       \
                uint32_t* ap = As + row * APAD + lc4;                          \
                ap[0] = f2tf(av[p].x); ap[1] = f2tf(av[p].y);                  \
                ap[2] = f2tf(av[p].z); ap[3] = f2tf(av[p].w);                  \
                uint32_t* bp = Bs + row * APAD + lc4;                          \
                bp[0] = f2tf(bv[p].x); bp[1] = f2tf(bv[p].y);                  \
                bp[2] = f2tf(bv[p].z); bp[3] = f2tf(bv[p].w);                  \
            }                                                                  \
            __syncthreads();                                                   \
        }                                                                      \
    }

// ---------------- plain GEMM (output projection) ------------------------------
__global__ __launch_bounds__(256)
void tf32_gemm(const float* __restrict__ A, const float* __restrict__ BT,
               float* __restrict__ C, int N) {
    extern __shared__ uint32_t smem[];
    int tid = threadIdx.x;
    int w = tid >> 5, lane = tid & 31;
    int g = lane >> 2, t = lane & 3;
    int wm = (w >> 2) * 64, wn = (w & 3) * 32;
    int bm = blockIdx.y * 128, bn = blockIdx.x * 128;
    const float* Ab = A + (size_t)bm * GK;
    const float* Bb = BT + (size_t)bn * GK;
    int lrow = tid >> 3, lc4 = (tid & 7) << 2;

    GEMM_MAINLOOP(Ab, Bb)

#pragma unroll
    for (int mi = 0; mi < 4; mi++) {
#pragma unroll
        for (int ni = 0; ni < 4; ni++) {
            int r0 = bm + wm + mi * 16 + g;
            int c0 = bn + wn + ni * 8 + t * 2;
            *(float2*)(C + (size_t)r0 * N + c0) =
                make_float2(acc[mi][ni][0], acc[mi][ni][1]);
            *(float2*)(C + (size_t)(r0 + 8) * N + c0) =
                make_float2(acc[mi][ni][2], acc[mi][ni][3]);
        }
    }
}

// ---------------- fused QKV GEMM + RoPE epilogue ------------------------------
#define QSCALE (0.125f * 1.44269504088896f)   // 1/sqrt(64) * log2(e)

__device__ __forceinline__ void qkv_write_pair(
    float* gq, float* gk, float* gv,
    const float* __restrict__ fc, const float* __restrict__ fs,
    int r, int c, float e0, float e1) {
    int b = r >> 11, s = r & 2047;
    if (c < HID) {
        int h = c >> 6, d = c & 63, p = d >> 1;
        float cs = fc[s * HALF + p], sn = fs[s * HALF + p];
        *(float2*)(gq + ((size_t)(b * NH + h) * SEQ + s) * HD + d) =
            make_float2((e0 * cs - e1 * sn) * QSCALE,
                        (e0 * sn + e1 * cs) * QSCALE);
    } else if (c < HID + NKV * HD) {
        int cc = c - HID;
        int kvh = cc >> 6, d = cc & 63, p = d >> 1;
        float cs = fc[s * HALF + p], sn = fs[s * HALF + p];
        *(float2*)(gk + ((size_t)(b * NKV + kvh) * SEQ + s) * HD + d) =
            make_float2(e0 * cs - e1 * sn, e0 * sn + e1 * cs);
    } else {
        int cc = c - HID - NKV * HD;
        int kvh = cc >> 6, d = cc & 63;
        *(float2*)(gv + ((size_t)(b * NKV + kvh) * SEQ + s) * HD + d) =
            make_float2(e0, e1);
    }
}

__global__ __launch_bounds__(256)
void qkv_rope_gemm(const float* __restrict__ A, const float* __restrict__ BT,
                   float* __restrict__ gq, float* __restrict__ gk,
                   float* __restrict__ gv,
                   const float* __restrict__ fc, const float* __restrict__ fs) {
    extern __shared__ uint32_t smem[];
    int tid = threadIdx.x;
    int w = tid >> 5, lane = tid & 31;
    int g = lane >> 2, t = lane & 3;
    int wm = (w >> 2) * 64, wn = (w & 3) * 32;
    int bm = blockIdx.y * 128, bn = blockIdx.x * 128;
    const float* Ab = A + (size_t)bm * GK;
    const float* Bb = BT + (size_t)bn * GK;
    int lrow = tid >> 3, lc4 = (tid & 7) << 2;

    GEMM_MAINLOOP(Ab, Bb)

#pragma unroll
    for (int mi = 0; mi < 4; mi++) {
#pragma unroll
        for (int ni = 0; ni < 4; ni++) {
            int r0 = bm + wm + mi * 16 + g;
            int c0 = bn + wn + ni * 8 + t * 2;
            qkv_write_pair(gq, gk, gv, fc, fs, r0, c0,
                           acc[mi][ni][0], acc[mi][ni][1]);
            qkv_write_pair(gq, gk, gv, fc, fs, r0 + 8, c0,
                           acc[mi][ni][2], acc[mi][ni][3]);
        }
    }
}

// ---------------- tensor-core flash attention v3 ------------------------------
// CTA: 128 q-rows x one (b,h), 8 warps x 16 rows, K-tile = 64 keys.
// Fragment-major smem: K/V fragments read as LDS.64, P as LDS.128.
// Q fragments in registers. Softmax in log2 domain (log2e folded into Q).
#define KF_OFF 0           // 8 ks x 8 ni x 64 words = 4096
#define VF_OFF 4096        // 4096 words
#define PF_OFF 8192        // 8 warps x 8 ks x 128 words = 8192
#define ATTN3_SMEM (16384 * 4)

__global__ __launch_bounds__(256, 2)
void attn_tc3_kernel(const float* __restrict__ Q, const float* __restrict__ K,
                     const float* __restrict__ V, float* __restrict__ O) {
    extern __shared__ uint32_t sm[];
    uint32_t* Kf = sm + KF_OFF;
    uint32_t* Vf = sm + VF_OFF;

    int tid = threadIdx.x;
    int w = tid >> 5, lane = tid & 31;
    int g = lane >> 2, t = lane & 3;
    int qt = gridDim.x - 1 - blockIdx.x;     // longest first
    int bh = blockIdx.y;
    int b = bh >> 5, h = bh & 31;
    int kvh = h >> 2;
    int q0 = qt * 128;
    int qrow = w * 16;

    uint32_t* Pw = sm + PF_OFF + w * 1024;

    const float* Qb = Q + ((size_t)(b * NH + h) * SEQ + q0) * HD;
    const float* Kb = K + (size_t)(b * NKV + kvh) * SEQ * HD;
    const float* Vb = V + (size_t)(b * NKV + kvh) * SEQ * HD;

    // Q fragments -> registers (once per CTA)
    uint32_t qf[8][4];
#pragma unroll
    for (int ks = 0; ks < 8; ks++) {
        int kk = ks * 8;
        qf[ks][0] = f2tf(Qb[(qrow + g) * HD + kk + t]);
        qf[ks][1] = f2tf(Qb[(qrow + 8 + g) * HD + kk + t]);
        qf[ks][2] = f2tf(Qb[(qrow + g) * HD + kk + t + 4]);
        qf[ks][3] = f2tf(Qb[(qrow + 8 + g) * HD + kk + t + 4]);
    }

    float oacc[8][4];
#pragma unroll
    for (int ni = 0; ni < 8; ni++)
#pragma unroll
        for (int e = 0; e < 4; e++) oacc[ni][e] = 0.0f;
    float m0 = -1e30f, m1 = -1e30f, l0 = 0.0f, l1 = 0.0f;

    int ktmax = (q0 >> 6) + 1;
    int ldrow = tid >> 4;              // 0..15
    int ldc4 = (tid & 15) << 2;        // d0 (mult of 4)

    // staging constants (per-thread)
    int ksK = ldc4 >> 3;                         // K: d-tile index
    int rK = (ldc4 >> 2) & 1;
    uint32_t swzK_st = (uint32_t)(((ksK & 3) << 3) | ((ksK & 4) >> 1));
    int niV = ldc4 >> 3;                         // V: d-tile index
    uint32_t swzV_st = (uint32_t)(((niV & 3) << 3) | ((niV & 4) >> 1));
    uint32_t swzP = (uint32_t)(((g >> 1) & 3) << 2);
    uint32_t pblk = (uint32_t)(((g * 4 + t) << 2) ^ swzP);

    for (int kt = 0; kt <= ktmax; kt++) {
        const float* Kp = Kb + (size_t)kt * 64 * HD;
        const float* Vp = Vb + (size_t)kt * 64 * HD;
        __syncthreads();   // previous tile consumed

        // ---- stage K and V into fragment-major smem ----
#pragma unroll
        for (int p = 0; p < 4; p++) {
            int n = p * 16 + ldrow;    // key index
            float4 kv = *(const float4*)(Kp + (size_t)n * HD + ldc4);
            uint32_t kw[4] = {f2tf(kv.x), f2tf(kv.y), f2tf(kv.z), f2tf(kv.w)};
            uint32_t baseK = (uint32_t)((ksK * 8 + (n >> 3)) * 64);
#pragma unroll
            for (int j = 0; j < 4; j++) {
                uint32_t lane_c = (uint32_t)(((n & 7) << 2) | j);
                Kf[baseK + (((lane_c << 1) | rK) ^ swzK_st)] = kw[j];
            }
            float4 vv = *(const float4*)(Vp + (size_t)n * HD + ldc4);
            uint32_t vw[4] = {f2tf(vv.x), f2tf(vv.y), f2tf(vv.z), f2tf(vv.w)};
            int rV = (n >> 2) & 1;
            uint32_t baseV = (uint32_t)(((n >> 3) * 8 + niV) * 64);
#pragma unroll
            for (int j = 0; j < 4; j++) {
                uint32_t lane_c = (uint32_t)((((ldc4 + j) & 7) << 2) | (n & 3));
                Vf[baseV + (((lane_c << 1) | rV) ^ swzV_st)] = vw[j];
            }
        }
        __syncthreads();

        // ---- S = Q K^T ----
        float sa[8][4];
#pragma unroll
        for (int ni = 0; ni < 8; ni++)
#pragma unroll
            for (int e = 0; e < 4; e++) sa[ni][e] = 0.0f;
#pragma unroll
        for (int ks = 0; ks < 8; ks++) {
            uint32_t swzK = (uint32_t)(((ks & 3) << 3) | ((ks & 4) >> 1));
            uint32_t base = (uint32_t)(ks * 8 * 64) + (((uint32_t)lane * 2) ^ swzK);
#pragma unroll
            for (int ni = 0; ni < 8; ni++) {
                uint2 bb = *(const uint2*)&Kf[base + ni * 64];
                uint32_t bfr[2] = {bb.x, bb.y};
                MMA_TF32(sa[ni], qf[ks], bfr);
            }
        }

        // ---- causal mask ----
        int r0 = q0 + qrow + g, r1 = r0 + 8;
        if (kt * 64 + 63 > r0) {
            int cb = kt * 64;
#pragma unroll
            for (int ni = 0; ni < 8; ni++) {
                int c0 = cb + ni * 8 + 2 * t, c1 = c0 + 1;
                if (c0 > r0) sa[ni][0] = -1e30f;
                if (c1 > r0) sa[ni][1] = -1e30f;
                if (c0 > r1) sa[ni][2] = -1e30f;
                if (c1 > r1) sa[ni][3] = -1e30f;
            }
        }

        // ---- online softmax (log2 domain) ----
        float mx0 = -1e30f, mx1 = -1e30f;
#pragma unroll
        for (int ni = 0; ni < 8; ni++) {
            mx0 = fmaxf(mx0, fmaxf(sa[ni][0], sa[ni][1]));
            mx1 = fmaxf(mx1, fmaxf(sa[ni][2], sa[ni][3]));
        }
        mx0 = fmaxf(mx0, __shfl_xor_sync(0xffffffffu, mx0, 1));
        mx0 = fmaxf(mx0, __shfl_xor_sync(0xffffffffu, mx0, 2));
        mx1 = fmaxf(mx1, __shfl_xor_sync(0xffffffffu, mx1, 1));
        mx1 = fmaxf(mx1, __shfl_xor_sync(0xffffffffu, mx1, 2));
        float mn0 = fmaxf(m0, mx0), mn1 = fmaxf(m1, mx1);
        float sc0 = ex2(m0 - mn0), sc1 = ex2(m1 - mn1);
        m0 = mn0; m1 = mn1;
        float sum0 = 0.0f, sum1 = 0.0f;
#pragma unroll
        for (int ni = 0; ni < 8; ni++) {
            sa[ni][0] = ex2(sa[ni][0] - mn0); sum0 += sa[ni][0];
            sa[ni][1] = ex2(sa[ni][1] - mn0); sum0 += sa[ni][1];
            sa[ni][2] = ex2(sa[ni][2] - mn1); sum1 += sa[ni][2];
            sa[ni][3] = ex2(sa[ni][3] - mn1); sum1 += sa[ni][3];
        }
        sum0 += __shfl_xor_sync(0xffffffffu, sum0, 1);
        sum0 += __shfl_xor_sync(0xffffffffu, sum0, 2);
        sum1 += __shfl_xor_sync(0xffffffffu, sum1, 1);
        sum1 += __shfl_xor_sync(0xffffffffu, sum1, 2);
        l0 = l0 * sc0 + sum0;
        l1 = l1 * sc1 + sum1;
#pragma unroll
        for (int ni = 0; ni < 8; ni++) {
            oacc[ni][0] *= sc0; oacc[ni][1] *= sc0;
            oacc[ni][2] *= sc1; oacc[ni][3] *= sc1;
        }

        // ---- P -> fragment-major smem (per-warp region) ----
#pragma unroll
        for (int ni = 0; ni < 8; ni++) {
#pragma unroll
            for (int eps = 0; eps < 2; eps++) {
                uint32_t lane_c = (uint32_t)(g * 4 + ((2 * t + eps) & 3));
                uint32_t blk = ((lane_c << 2) ^ swzP) + (uint32_t)(2 * (t >= 2));
                uint32_t a0 = (uint32_t)(ni * 128) + blk;
                Pw[a0]     = f2tf(sa[ni][eps]);       // mh=0
                Pw[a0 + 1] = f2tf(sa[ni][2 + eps]);   // mh=1
            }
        }
        __syncwarp();

        // ---- O += P V ----
#pragma unroll
        for (int ks = 0; ks < 8; ks++) {
            uint4 aa = *(const uint4*)&Pw[ks * 128 + pblk];
            uint32_t a[4] = {aa.x, aa.y, aa.z, aa.w};
#pragma unroll
            for (int ni = 0; ni < 8; ni++) {
                uint32_t swzV = (uint32_t)(((ni & 3) << 3) | ((ni & 4) >> 1));
                uint2 bb = *(const uint2*)&Vf[(ks * 8 + ni) * 64 +
                                              (((uint32_t)lane * 2) ^ swzV)];
                uint32_t bfr[2] = {bb.x, bb.y};
                MMA_TF32(oacc[ni], a, bfr);
            }
        }
        __syncwarp();
    }

    // ---- normalize + write [B,S,H*D] ----
    float rl0 = 1.0f / l0, rl1 = 1.0f / l1;
    int r0 = q0 + qrow + g, r1 = r0 + 8;
#pragma unroll
    for (int ni = 0; ni < 8; ni++) {
        int col = ni * 8 + 2 * t;
        *(float2*)(O + ((size_t)(b * SEQ + r0) * NH + h) * HD + col) =
            make_float2(oacc[ni][0] * rl0, oacc[ni][1] * rl0);
        *(float2*)(O + ((size_t)(b * SEQ + r1) * NH + h) * HD + col) =
            make_float2(oacc[ni][2] * rl1, oacc[ni][3] * rl1);
    }
}

// ---------------- launcher ---------------------------------------------------
extern "C" void kernel_launch(void* const* d_in, const int* in_sizes, int n_in,
                              void* d_out, int out_size) {
    const float* x  = (const float*)d_in[0];
    const float* wq = (const float*)d_in[1];
    const float* wk = (const float*)d_in[2];
    const float* wv = (const float*)d_in[3];
    const float* wo = (const float*)d_in[4];
    const float* fc = (const float*)d_in[5];
    const float* fs = (const float*)d_in[6];
    float* out = (float*)d_out;

    float *q, *k, *v, *ao, *wqkvT, *woT;
    cudaGetSymbolAddress((void**)&q,  g_q);
    cudaGetSymbolAddress((void**)&k,  g_k);
    cudaGetSymbolAddress((void**)&v,  g_v);
    cudaGetSymbolAddress((void**)&ao, g_ao);
    cudaGetSymbolAddress((void**)&wqkvT, g_wqkvT);
    cudaGetSymbolAddress((void**)&woT, g_woT);

    const int M = BATCH * SEQ;  // 4096

    transpose_kernel<<<dim3(HID / 32, HID / 32), dim3(32, 8)>>>(wq, wqkvT, HID, HID);
    transpose_kernel<<<dim3((NKV * HD) / 32, HID / 32), dim3(32, 8)>>>(
        wk, wqkvT + (size_t)HID * HID, HID, NKV * HD);
    transpose_kernel<<<dim3((NKV * HD) / 32, HID / 32), dim3(32, 8)>>>(
        wv, wqkvT + (size_t)(HID + NKV * HD) * HID, HID, NKV * HD);
    transpose_kernel<<<dim3(HID / 32, HID / 32), dim3(32, 8)>>>(wo, woT, HID, HID);

    cudaFuncSetAttribute(qkv_rope_gemm, cudaFuncAttributeMaxDynamicSharedMemorySize,
                         GEMM_SMEM);
    cudaFuncSetAttribute(tf32_gemm, cudaFuncAttributeMaxDynamicSharedMemorySize,
                         GEMM_SMEM);

    // fused QKV projection + RoPE (+log2e scale on Q) epilogue
    qkv_rope_gemm<<<dim3(NQKV / 128, M / 128), 256, GEMM_SMEM>>>(
        x, wqkvT, q, k, v, fc, fs);

    // flash attention v3 (fragment-major smem, Q in registers)
    cudaFuncSetAttribute(attn_tc3_kernel, cudaFuncAttributeMaxDynamicSharedMemorySize,
                         ATTN3_SMEM);
    attn_tc3_kernel<<<dim3(SEQ / 128, BATCH * NH), 256, ATTN3_SMEM>>>(q, k, v, ao);

    // output projection
    tf32_gemm<<<dim3(HID / 128, M / 128), 256, GEMM_SMEM>>>(ao, woT, out, HID);
}

// round 15
// speedup vs baseline: 1.6953x; 1.6825x over previous
#include <cuda_runtime.h>
#include <cstdint>

#define BATCH 2
#define SEQ 2048
#define HID 2048
#define NH 32
#define NKV 8
#define HD 64
#define HALF 32
#define GK 2048
#define CHUNK 32
#define NCHUNK (GK / CHUNK)
#define NQKV 3072

// ---------------- scratch (static device globals; no allocation) -------------
__device__ float g_q[BATCH * NH * SEQ * HD];     // roped, scaled  [B,H,S,D]
__device__ float g_k[BATCH * NKV * SEQ * HD];    // roped          [B,KV,S,D]
__device__ float g_vt[BATCH * NKV * HD * SEQ];   // TRANSPOSED     [B,KV,D,S]
__device__ float g_ao[BATCH * SEQ * HID];        // attn out [B,S,H*D]
__device__ float g_wqkvT[NQKV * HID];
__device__ float g_woT[HID * HID];

// ---------------- helpers ----------------------------------------------------
__device__ __forceinline__ uint32_t f2h2(float lo, float hi) {
    uint32_t d;
    asm("cvt.rn.f16x2.f32 %0, %1, %2;" : "=r"(d) : "f"(hi), "f"(lo));
    return d;
}
__device__ __forceinline__ float ex2(float x) {
    float r;
    asm("ex2.approx.f32 %0, %1;" : "=f"(r) : "f"(x));
    return r;
}

#define MMA_F16(d, a, b)                                                       \
    asm volatile("mma.sync.aligned.m16n8k16.row.col.f32.f16.f16.f32 "          \
        "{%0,%1,%2,%3}, {%4,%5,%6,%7}, {%8,%9}, {%0,%1,%2,%3};"                \
        : "+f"((d)[0]), "+f"((d)[1]), "+f"((d)[2]), "+f"((d)[3])               \
        : "r"((a)[0]), "r"((a)[1]), "r"((a)[2]), "r"((a)[3]),                  \
          "r"((b)[0]), "r"((b)[1]))

// ---------------- weight transpose: out[C][R] = in[R][C] ---------------------
__global__ void transpose_kernel(const float* __restrict__ in, float* __restrict__ out,
                                 int R, int C) {
    __shared__ float t[32][33];
    int bx = blockIdx.x * 32, by = blockIdx.y * 32;
#pragma unroll
    for (int j = 0; j < 32; j += 8)
        t[threadIdx.y + j][threadIdx.x] =
            in[(size_t)(by + threadIdx.y + j) * C + bx + threadIdx.x];
    __syncthreads();
#pragma unroll
    for (int j = 0; j < 32; j += 8)
        out[(size_t)(bx + threadIdx.y + j) * R + by + threadIdx.x] =
            t[threadIdx.x][threadIdx.y + j];
}

// ---------------- fp16 GEMM mainloop (shared by 2 kernels) --------------------
// smem rows: 32 halves = 16 words + pad -> WPITCH 20 words (conflict-free frags)
#define WPITCH 20
#define TILE_W (128 * WPITCH)
#define GEMM_SMEM (2 * 2 * TILE_W * 4)

#define GEMM_MAINLOOP(Aptr, Bptr)                                              \
    float acc[4][4][4];                                                        \
    _Pragma("unroll")                                                          \
    for (int mi = 0; mi < 4; mi++)                                             \
        _Pragma("unroll")                                                      \
        for (int ni = 0; ni < 4; ni++)                                         \
            _Pragma("unroll")                                                  \
            for (int e = 0; e < 4; e++) acc[mi][ni][e] = 0.0f;                 \
    float4 av[4], bv[4];                                                       \
    _Pragma("unroll")                                                          \
    for (int p = 0; p < 4; p++) {                                              \
        int row = p * 32 + lrow;                                               \
        av[p] = *(const float4*)(Aptr + (size_t)row * GK + lc4);               \
        bv[p] = *(const float4*)(Bptr + (size_t)row * GK + lc4);               \
    }                                                                          \
    {                                                                          \
        uint32_t* As = smem;                                                   \
        uint32_t* Bs = smem + TILE_W;                                          \
        _Pragma("unroll")                                                      \
        for (int p = 0; p < 4; p++) {                                          \
            int row = p * 32 + lrow;                                           \
            uint32_t* ap = As + row * WPITCH + (lc4 >> 1);                     \
            ap[0] = f2h2(av[p].x, av[p].y);                                    \
            ap[1] = f2h2(av[p].z, av[p].w);                                    \
            uint32_t* bp = Bs + row * WPITCH + (lc4 >> 1);                     \
            bp[0] = f2h2(bv[p].x, bv[p].y);                                    \
            bp[1] = f2h2(bv[p].z, bv[p].w);                                    \
        }                                                                      \
    }                                                                          \
    __syncthreads();                                                           \
    for (int i = 0; i < NCHUNK; i++) {                                         \
        if (i + 1 < NCHUNK) {                                                  \
            int k0 = (i + 1) * CHUNK;                                          \
            _Pragma("unroll")                                                  \
            for (int p = 0; p < 4; p++) {                                      \
                int row = p * 32 + lrow;                                       \
                av[p] = *(const float4*)(Aptr + (size_t)row * GK + k0 + lc4);  \
                bv[p] = *(const float4*)(Bptr + (size_t)row * GK + k0 + lc4);  \
            }                                                                  \
        }                                                                      \
        {                                                                      \
            uint32_t* As = smem + (i & 1) * 2 * TILE_W;                        \
            uint32_t* Bs = As + TILE_W;                                        \
            _Pragma("unroll")                                                  \
            for (int ks = 0; ks < 2; ks++) {                                   \
                int kw = ks * 8;                                               \
                uint32_t afr[4][4];                                            \
                _Pragma("unroll")                                              \
                for (int mi = 0; mi < 4; mi++) {                               \
                    int r0 = wm + mi * 16 + g;                                 \
                    afr[mi][0] = As[r0 * WPITCH + kw + t];                     \
                    afr[mi][1] = As[(r0 + 8) * WPITCH + kw + t];               \
                    afr[mi][2] = As[r0 * WPITCH + kw + t + 4];                 \
                    afr[mi][3] = As[(r0 + 8) * WPITCH + kw + t + 4];           \
                }                                                              \
                uint32_t bfr[4][2];                                            \
                _Pragma("unroll")                                              \
                for (int ni = 0; ni < 4; ni++) {                               \
                    int n0 = wn + ni * 8 + g;                                  \
                    bfr[ni][0] = Bs[n0 * WPITCH + kw + t];                     \
                    bfr[ni][1] = Bs[n0 * WPITCH + kw + t + 4];                 \
                }                                                              \
                _Pragma("unroll")                                              \
                for (int mi = 0; mi < 4; mi++)                                 \
                    _Pragma("unroll")                                          \
                    for (int ni = 0; ni < 4; ni++)                             \
                        MMA_F16(acc[mi][ni], afr[mi], bfr[ni]);                \
            }                                                                  \
        }                                                                      \
        if (i + 1 < NCHUNK) {                                                  \
            __syncthreads();                                                   \
            uint32_t* As = smem + ((i + 1) & 1) * 2 * TILE_W;                  \
            uint32_t* Bs = As + TILE_W;                                        \
            _Pragma("unroll")                                                  \
            for (int p = 0; p < 4; p++) {                                      \
                int row = p * 32 + lrow;                                       \
                uint32_t* ap = As + row * WPITCH + (lc4 >> 1);                 \
                ap[0] = f2h2(av[p].x, av[p].y);                                \
                ap[1] = f2h2(av[p].z, av[p].w);                                \
                uint32_t* bp = Bs + row * WPITCH + (lc4 >> 1);                 \
                bp[0] = f2h2(bv[p].x, bv[p].y);                                \
                bp[1] = f2h2(bv[p].z, bv[p].w);                                \
            }                                                                  \
            __syncthreads();                                                   \
        }                                                                      \
    }

// ---------------- plain GEMM (output projection) ------------------------------
__global__ __launch_bounds__(256)
void f16_gemm(const float* __restrict__ A, const float* __restrict__ BT,
              float* __restrict__ C, int N) {
    extern __shared__ uint32_t smem[];
    int tid = threadIdx.x;
    int w = tid >> 5, lane = tid & 31;
    int g = lane >> 2, t = lane & 3;
    int wm = (w >> 2) * 64, wn = (w & 3) * 32;
    int bm = blockIdx.y * 128, bn = blockIdx.x * 128;
    const float* Ab = A + (size_t)bm * GK;
    const float* Bb = BT + (size_t)bn * GK;
    int lrow = tid >> 3, lc4 = (tid & 7) << 2;

    GEMM_MAINLOOP(Ab, Bb)

#pragma unroll
    for (int mi = 0; mi < 4; mi++) {
#pragma unroll
        for (int ni = 0; ni < 4; ni++) {
            int r0 = bm + wm + mi * 16 + g;
            int c0 = bn + wn + ni * 8 + t * 2;
            *(float2*)(C + (size_t)r0 * N + c0) =
                make_float2(acc[mi][ni][0], acc[mi][ni][1]);
            *(float2*)(C + (size_t)(r0 + 8) * N + c0) =
                make_float2(acc[mi][ni][2], acc[mi][ni][3]);
        }
    }
}

// ---------------- fused QKV GEMM + RoPE epilogue (V written transposed) -------
#define QSCALE (0.125f * 1.44269504088896f)   // 1/sqrt(64) * log2(e)

__device__ __forceinline__ void qkv_write_pair(
    float* gq, float* gk, float* gvt,
    const float* __restrict__ fc, const float* __restrict__ fs,
    int r, int c, float e0, float e1) {
    int b = r >> 11, s = r & 2047;
    if (c < HID) {
        int h = c >> 6, d = c & 63, p = d >> 1;
        float cs = fc[s * HALF + p], sn = fs[s * HALF + p];
        *(float2*)(gq + ((size_t)(b * NH + h) * SEQ + s) * HD + d) =
            make_float2((e0 * cs - e1 * sn) * QSCALE,
                        (e0 * sn + e1 * cs) * QSCALE);
    } else if (c < HID + NKV * HD) {
        int cc = c - HID;
        int kvh = cc >> 6, d = cc & 63, p = d >> 1;
        float cs = fc[s * HALF + p], sn = fs[s * HALF + p];
        *(float2*)(gk + ((size_t)(b * NKV + kvh) * SEQ + s) * HD + d) =
            make_float2(e0 * cs - e1 * sn, e0 * sn + e1 * cs);
    } else {                                  // V: transposed [B,KV,D,S]
        int cc = c - HID - NKV * HD;
        int kvh = cc >> 6, d = cc & 63;
        size_t base = ((size_t)(b * NKV + kvh) * HD + d) * SEQ + s;
        gvt[base] = e0;
        gvt[base + SEQ] = e1;                 // d+1 row
    }
}

__global__ __launch_bounds__(256)
void qkv_rope_gemm(const float* __restrict__ A, const float* __restrict__ BT,
                   float* __restrict__ gq, float* __restrict__ gk,
                   float* __restrict__ gvt,
                   const float* __restrict__ fc, const float* __restrict__ fs) {
    extern __shared__ uint32_t smem[];
    int tid = threadIdx.x;
    int w = tid >> 5, lane = tid & 31;
    int g = lane >> 2, t = lane & 3;
    int wm = (w >> 2) * 64, wn = (w & 3) * 32;
    int bm = blockIdx.y * 128, bn = blockIdx.x * 128;
    const float* Ab = A + (size_t)bm * GK;
    const float* Bb = BT + (size_t)bn * GK;
    int lrow = tid >> 3, lc4 = (tid & 7) << 2;

    GEMM_MAINLOOP(Ab, Bb)

#pragma unroll
    for (int mi = 0; mi < 4; mi++) {
#pragma unroll
        for (int ni = 0; ni < 4; ni++) {
            int r0 = bm + wm + mi * 16 + g;
            int c0 = bn + wn + ni * 8 + t * 2;
            qkv_write_pair(gq, gk, gvt, fc, fs, r0, c0,
                           acc[mi][ni][0], acc[mi][ni][1]);
            qkv_write_pair(gq, gk, gvt, fc, fs, r0 + 8, c0,
                           acc[mi][ni][2], acc[mi][ni][3]);
        }
    }
}

// ---------------- fp16 tensor-core flash attention ----------------------------
// CTA: 128 q-rows x one (b,h), 8 warps x 16 rows, K-tile = 64 keys.
// K smem [key][32w] pitch 36; V^T smem [d][32w] pitch 36; P [16][32w]/warp.
// All fragment LDS.32 conflict-free (4g+t bank pattern). Q frags in registers.
#define AP 36
#define KS_OFF 0
#define VS_OFF (64 * AP)
#define PS_OFF (2 * 64 * AP)
#define ATTN_SMEM ((2 * 64 * AP + 8 * 16 * AP) * 4)   // 36864 B

__global__ __launch_bounds__(256, 2)
void attn_f16_kernel(const float* __restrict__ Q, const float* __restrict__ K,
                     const float* __restrict__ Vt, float* __restrict__ O) {
    extern __shared__ uint32_t sm[];
    uint32_t* Ks = sm + KS_OFF;
    uint32_t* Vs = sm + VS_OFF;

    int tid = threadIdx.x;
    int w = tid >> 5, lane = tid & 31;
    int g = lane >> 2, t = lane & 3;
    int qt = gridDim.x - 1 - blockIdx.x;     // longest first
    int bh = blockIdx.y;
    int b = bh >> 5, h = bh & 31;
    int kvh = h >> 2;
    int q0 = qt * 128;
    int qrow = w * 16;

    uint32_t* Pw = sm + PS_OFF + w * 16 * AP;

    const float* Qb = Q + ((size_t)(b * NH + h) * SEQ + q0) * HD;
    const float* Kb = K + (size_t)(b * NKV + kvh) * SEQ * HD;
    const float* Vb = Vt + (size_t)(b * NKV + kvh) * HD * SEQ;

    // Q fragments (m16n8k16 A) -> registers once
    uint32_t qf[4][4];
#pragma unroll
    for (int ks = 0; ks < 4; ks++) {
        int d0 = ks * 16 + 2 * t;
        float2 x0 = *(const float2*)(Qb + (qrow + g) * HD + d0);
        float2 x1 = *(const float2*)(Qb + (qrow + 8 + g) * HD + d0);
        float2 x2 = *(const float2*)(Qb + (qrow + g) * HD + d0 + 8);
        float2 x3 = *(const float2*)(Qb + (qrow + 8 + g) * HD + d0 + 8);
        qf[ks][0] = f2h2(x0.x, x0.y);
        qf[ks][1] = f2h2(x1.x, x1.y);
        qf[ks][2] = f2h2(x2.x, x2.y);
        qf[ks][3] = f2h2(x3.x, x3.y);
    }

    float oacc[8][4];
#pragma unroll
    for (int ni = 0; ni < 8; ni++)
#pragma unroll
        for (int e = 0; e < 4; e++) oacc[ni][e] = 0.0f;
    float m0 = -1e30f, m1 = -1e30f, l0 = 0.0f, l1 = 0.0f;

    int ktmax = (q0 >> 6) + 1;
    int ldrow = tid >> 4;              // 0..15
    int ldc4 = (tid & 15) << 2;        // 0..60 step 4

    for (int kt = 0; kt <= ktmax; kt++) {
        const float* Kp = Kb + (size_t)kt * 64 * HD;
        const float* Vp = Vb + (size_t)kt * 64;
        __syncthreads();   // previous tile consumed

        // ---- stage K [key][d] and V^T [d][key] as packed halves ----
#pragma unroll
        for (int p = 0; p < 4; p++) {
            int r = p * 16 + ldrow;
            float4 kv = *(const float4*)(Kp + (size_t)r * HD + ldc4);
            uint32_t* kp_ = Ks + r * AP + (ldc4 >> 1);
            kp_[0] = f2h2(kv.x, kv.y);
            kp_[1] = f2h2(kv.z, kv.w);
            float4 vv = *(const float4*)(Vp + (size_t)r * SEQ + ldc4);
            uint32_t* vp_ = Vs + r * AP + (ldc4 >> 1);
            vp_[0] = f2h2(vv.x, vv.y);
            vp_[1] = f2h2(vv.z, vv.w);
        }
        __syncthreads();

        // ---- S = Q K^T  (k-dim = d, 4 steps of 16) ----
        float sa[8][4];
#pragma unroll
        for (int ni = 0; ni < 8; ni++)
#pragma unroll
            for (int e = 0; e < 4; e++) sa[ni][e] = 0.0f;
#pragma unroll
        for (int ks = 0; ks < 4; ks++) {
            int kw = ks * 8;
#pragma unroll
            for (int ni = 0; ni < 8; ni++) {
                int n0 = ni * 8 + g;
                uint32_t bfr[2];
                bfr[0] = Ks[n0 * AP + kw + t];
                bfr[1] = Ks[n0 * AP + kw + t + 4];
                MMA_F16(sa[ni], qf[ks], bfr);
            }
        }

        // ---- causal mask ----
        int r0 = q0 + qrow + g, r1 = r0 + 8;
        if (kt * 64 + 63 > r0) {
            int cb = kt * 64;
#pragma unroll
            for (int ni = 0; ni < 8; ni++) {
                int c0 = cb + ni * 8 + 2 * t, c1 = c0 + 1;
                if (c0 > r0) sa[ni][0] = -1e30f;
                if (c1 > r0) sa[ni][1] = -1e30f;
                if (c0 > r1) sa[ni][2] = -1e30f;
                if (c1 > r1) sa[ni][3] = -1e30f;
            }
        }

        // ---- online softmax (log2 domain; log2e folded into Q) ----
        float mx0 = -1e30f, mx1 = -1e30f;
#pragma unroll
        for (int ni = 0; ni < 8; ni++) {
            mx0 = fmaxf(mx0, fmaxf(sa[ni][0], sa[ni][1]));
            mx1 = fmaxf(mx1, fmaxf(sa[ni][2], sa[ni][3]));
        }
        mx0 = fmaxf(mx0, __shfl_xor_sync(0xffffffffu, mx0, 1));
        mx0 = fmaxf(mx0, __shfl_xor_sync(0xffffffffu, mx0, 2));
        mx1 = fmaxf(mx1, __shfl_xor_sync(0xffffffffu, mx1, 1));
        mx1 = fmaxf(mx1, __shfl_xor_sync(0xffffffffu, mx1, 2));
        float mn0 = fmaxf(m0, mx0), mn1 = fmaxf(m1, mx1);
        float sc0 = ex2(m0 - mn0), sc1 = ex2(m1 - mn1);
        m0 = mn0; m1 = mn1;
        float sum0 = 0.0f, sum1 = 0.0f;
#pragma unroll
        for (int ni = 0; ni < 8; ni++) {
            sa[ni][0] = ex2(sa[ni][0] - mn0); sum0 += sa[ni][0];
            sa[ni][1] = ex2(sa[ni][1] - mn0); sum0 += sa[ni][1];
            sa[ni][2] = ex2(sa[ni][2] - mn1); sum1 += sa[ni][2];
            sa[ni][3] = ex2(sa[ni][3] - mn1); sum1 += sa[ni][3];
        }
        sum0 += __shfl_xor_sync(0xffffffffu, sum0, 1);
        sum0 += __shfl_xor_sync(0xffffffffu, sum0, 2);
        sum1 += __shfl_xor_sync(0xffffffffu, sum1, 1);
        sum1 += __shfl_xor_sync(0xffffffffu, sum1, 2);
        l0 = l0 * sc0 + sum0;
        l1 = l1 * sc1 + sum1;
#pragma unroll
        for (int ni = 0; ni < 8; ni++) {
            oacc[ni][0] *= sc0; oacc[ni][1] *= sc0;
            oacc[ni][2] *= sc1; oacc[ni][3] *= sc1;
        }

        // ---- P -> packed halves [16 rows][32 words], per-warp region ----
        // thread owns key pair (ni*8+2t, +1) on rows g and g+8 -> word 4ni+t
#pragma unroll
        for (int ni = 0; ni < 8; ni++) {
            int c = 4 * ni + t;
            Pw[g * AP + c]       = f2h2(sa[ni][0], sa[ni][1]);
            Pw[(g + 8) * AP + c] = f2h2(sa[ni][2], sa[ni][3]);
        }
        __syncwarp();

        // ---- O += P V  (k-dim = key, 4 steps of 16) ----
#pragma unroll
        for (int ks = 0; ks < 4; ks++) {
            int kw = ks * 8;
            uint32_t a[4];
            a[0] = Pw[g * AP + kw + t];
            a[1] = Pw[(g + 8) * AP + kw + t];
            a[2] = Pw[g * AP + kw + t + 4];
            a[3] = Pw[(g + 8) * AP + kw + t + 4];
#pragma unroll
            for (int ni = 0; ni < 8; ni++) {
                int n0 = ni * 8 + g;     // d index -> Vs row
                uint32_t bfr[2];
                bfr[0] = Vs[n0 * AP + kw + t];
                bfr[1] = Vs[n0 * AP + kw + t + 4];
                MMA_F16(oacc[ni], a, bfr);
            }
        }
        __syncwarp();
    }

    // ---- normalize + write [B,S,H*D] ----
    float rl0 = 1.0f / l0, rl1 = 1.0f / l1;
    int r0 = q0 + qrow + g, r1 = r0 + 8;
#pragma unroll
    for (int ni = 0; ni < 8; ni++) {
        int col = ni * 8 + 2 * t;
        *(float2*)(O + ((size_t)(b * SEQ + r0) * NH + h) * HD + col) =
            make_float2(oacc[ni][0] * rl0, oacc[ni][1] * rl0);
        *(float2*)(O + ((size_t)(b * SEQ + r1) * NH + h) * HD + col) =
            make_float2(oacc[ni][2] * rl1, oacc[ni][3] * rl1);
    }
}

// ---------------- launcher ---------------------------------------------------
extern "C" void kernel_launch(void* const* d_in, const int* in_sizes, int n_in,
                              void* d_out, int out_size) {
    const float* x  = (const float*)d_in[0];
    const float* wq = (const float*)d_in[1];
    const float* wk = (const float*)d_in[2];
    const float* wv = (const float*)d_in[3];
    const float* wo = (const float*)d_in[4];
    const float* fc = (const float*)d_in[5];
    const float* fs = (const float*)d_in[6];
    float* out = (float*)d_out;

    float *q, *k, *vt, *ao, *wqkvT, *woT;
    cudaGetSymbolAddress((void**)&q,  g_q);
    cudaGetSymbolAddress((void**)&k,  g_k);
    cudaGetSymbolAddress((void**)&vt, g_vt);
    cudaGetSymbolAddress((void**)&ao, g_ao);
    cudaGetSymbolAddress((void**)&wqkvT, g_wqkvT);
    cudaGetSymbolAddress((void**)&woT, g_woT);

    const int M = BATCH * SEQ;  // 4096

    transpose_kernel<<<dim3(HID / 32, HID / 32), dim3(32, 8)>>>(wq, wqkvT, HID, HID);
    transpose_kernel<<<dim3((NKV * HD) / 32, HID / 32), dim3(32, 8)>>>(
        wk, wqkvT + (size_t)HID * HID, HID, NKV * HD);
    transpose_kernel<<<dim3((NKV * HD) / 32, HID / 32), dim3(32, 8)>>>(
        wv, wqkvT + (size_t)(HID + NKV * HD) * HID, HID, NKV * HD);
    transpose_kernel<<<dim3(HID / 32, HID / 32), dim3(32, 8)>>>(wo, woT, HID, HID);

    cudaFuncSetAttribute(qkv_rope_gemm, cudaFuncAttributeMaxDynamicSharedMemorySize,
                         GEMM_SMEM);
    cudaFuncSetAttribute(f16_gemm, cudaFuncAttributeMaxDynamicSharedMemorySize,
                         GEMM_SMEM);

    // fused QKV projection + RoPE epilogue (V written transposed)
    qkv_rope_gemm<<<dim3(NQKV / 128, M / 128), 256, GEMM_SMEM>>>(
        x, wqkvT, q, k, vt, fc, fs);

    // fp16 tensor-core flash attention
    cudaFuncSetAttribute(attn_f16_kernel, cudaFuncAttributeMaxDynamicSharedMemorySize,
                         ATTN_SMEM);
    attn_f16_kernel<<<dim3(SEQ / 128, BATCH * NH), 256, ATTN_SMEM>>>(q, k, vt, ao);

    // output projection
    f16_gemm<<<dim3(HID / 128, M / 128), 256, GEMM_SMEM>>>(ao, woT, out, HID);
}